// round 15
// baseline (speedup 1.0000x reference)
#include <cuda_runtime.h>
#include <cuda_bf16.h>
#include <cstdint>

// ---------------- scratch (no allocation allowed -> __device__ globals) -----
__device__ float g_q[1024 * 128];
__device__ float g_k[1024 * 128];
__device__ float g_v[1024 * 128];
__device__ float g_ctx[1024 * 128];
__device__ float g_att[1024 * 128];
__device__ float g_t1[1024 * 256];   // holds t1 + b1 (b1 folded in)
__device__ float g_n1[1024 * 256];

// ---------------- QKV projection: q/k/v = x @ Wqkv^T + b --------------------
__global__ __launch_bounds__(384) void qkv_kernel(const float* __restrict__ x,
                                                  const float* __restrict__ W,
                                                  const float* __restrict__ b) {
    __shared__ float xs[8 * 128];
    int rb = blockIdx.x * 8;
    for (int i = threadIdx.x; i < 1024; i += 384) xs[i] = x[rb * 128 + i];
    __syncthreads();
    int j = threadIdx.x;
    const float4* w4 = (const float4*)(W + j * 128);
    const float4* xs4 = (const float4*)xs;
    float acc[8] = {0, 0, 0, 0, 0, 0, 0, 0};
#pragma unroll 8
    for (int i4 = 0; i4 < 32; i4++) {
        float4 w = w4[i4];
#pragma unroll
        for (int r = 0; r < 8; r++) {
            float4 xv = xs4[r * 32 + i4];
            acc[r] += w.x * xv.x + w.y * xv.y + w.z * xv.z + w.w * xv.w;
        }
    }
    float bj = b[j];
    float* dst;
    int col;
    if (j < 128) { dst = g_q; col = j; }
    else if (j < 256) { dst = g_k; col = j - 128; }
    else { dst = g_v; col = j - 256; }
#pragma unroll
    for (int r = 0; r < 8; r++) dst[(rb + r) * 128 + col] = acc[r] + bj;
}

// ---------------- attention (fp32; attn_w is an output) ----------------------
#define HSTRIDE 8200
#define ATTN_SMEM_BYTES ((4 * HSTRIDE + 128 * 132 + 256) * 4)
__global__ __launch_bounds__(256) void attn_kernel(float* __restrict__ attnw) {
    extern __shared__ float sm[];
    float* Ps4 = sm;                    // 4 heads x [8][1024], head stride 8200
    float* Vs = sm + 4 * HSTRIDE;       // [128][132]; doubles as Ks [128][33]
    float* Qs = Vs + 128 * 132;         // [8][32]
    float* Ks = Vs;
    int tid = threadIdx.x, lane = tid & 31, warp = tid >> 5;
    int qbase = blockIdx.x * 8;

    for (int h = 0; h < 4; h++) {
        float* Psh = Ps4 + h * HSTRIDE;
        __syncthreads();
        {
            int r = tid >> 5, d = tid & 31;
            Qs[tid] = g_q[(qbase + r) * 128 + h * 32 + d] * 0.17677669529663687f;
        }
        for (int kc = 0; kc < 8; kc++) {
            __syncthreads();
            for (int i = tid; i < 4096; i += 256) {
                int kk = i >> 5, d = i & 31;
                Ks[kk * 33 + d] = g_k[(kc * 128 + kk) * 128 + h * 32 + d];
            }
            __syncthreads();
            int r0 = (tid >> 6) * 2;
            int k0 = tid & 63;
            float s00 = 0, s01 = 0, s10 = 0, s11 = 0;
#pragma unroll
            for (int d = 0; d < 32; d++) {
                float qa = Qs[r0 * 32 + d], qb = Qs[(r0 + 1) * 32 + d];
                float ka = Ks[k0 * 33 + d], kb = Ks[(k0 + 64) * 33 + d];
                s00 += qa * ka; s01 += qa * kb;
                s10 += qb * ka; s11 += qb * kb;
            }
            int cb = kc * 128;
            Psh[r0 * 1024 + cb + k0] = s00;
            Psh[r0 * 1024 + cb + k0 + 64] = s01;
            Psh[(r0 + 1) * 1024 + cb + k0] = s10;
            Psh[(r0 + 1) * 1024 + cb + k0 + 64] = s11;
        }
        __syncthreads();
        {
            float* row = Psh + warp * 1024;
            float m = -1e30f;
            for (int i = lane; i < 1024; i += 32) m = fmaxf(m, row[i]);
#pragma unroll
            for (int o = 16; o > 0; o >>= 1) m = fmaxf(m, __shfl_xor_sync(0xffffffffu, m, o));
            float s = 0.f;
            for (int i = lane; i < 1024; i += 32) {
                float e = __expf(row[i] - m);
                row[i] = e;
                s += e;
            }
#pragma unroll
            for (int o = 16; o > 0; o >>= 1) s += __shfl_xor_sync(0xffffffffu, s, o);
            float inv = 1.f / s;
            for (int i = lane; i < 1024; i += 32) row[i] *= inv;
        }
    }
    __syncthreads();

    {   // single-pass attn_w = mean over heads
        float* arow = attnw + (qbase + warp) * 1024;
        int rb = warp * 1024;
        for (int i = lane; i < 1024; i += 32) {
            float s = Ps4[rb + i] + Ps4[HSTRIDE + rb + i] +
                      Ps4[2 * HSTRIDE + rb + i] + Ps4[3 * HSTRIDE + rb + i];
            arow[i] = 0.25f * s;
        }
    }

    // ctx[r, d0..d0+3] = sum_k p_head[r,k] * V[k, d0..d0+3]
    int r = tid >> 5, dq = tid & 31, head = dq >> 3;
    const float* prowbase = Ps4 + head * HSTRIDE + r * 1024;
    float4 acc = {0.f, 0.f, 0.f, 0.f};
    for (int kc = 0; kc < 8; kc++) {
        __syncthreads();
        for (int i = tid; i < 4096; i += 256) {
            int kk = i >> 5, c4 = i & 31;
            ((float4*)(Vs + kk * 132))[c4] =
                *(const float4*)(g_v + (kc * 128 + kk) * 128 + c4 * 4);
        }
        __syncthreads();
        const float* prow = prowbase + kc * 128;
#pragma unroll 4
        for (int k = 0; k < 128; k++) {
            float p = prow[k];
            float4 v = ((const float4*)(Vs + k * 132))[dq];
            acc.x += p * v.x; acc.y += p * v.y;
            acc.z += p * v.z; acc.w += p * v.w;
        }
    }
    *(float4*)(g_ctx + (qbase + r) * 128 + dq * 4) = acc;
}

// ---------------- out projection ---------------------------------------------
__global__ __launch_bounds__(128) void outproj_kernel(const float* __restrict__ W,
                                                      const float* __restrict__ b) {
    __shared__ float xs[8 * 128];
    int rb = blockIdx.x * 8;
    for (int i = threadIdx.x; i < 1024; i += 128) xs[i] = g_ctx[rb * 128 + i];
    __syncthreads();
    int j = threadIdx.x;
    const float4* w4 = (const float4*)(W + j * 128);
    const float4* xs4 = (const float4*)xs;
    float acc[8] = {0, 0, 0, 0, 0, 0, 0, 0};
#pragma unroll 8
    for (int i4 = 0; i4 < 32; i4++) {
        float4 w = w4[i4];
#pragma unroll
        for (int r = 0; r < 8; r++) {
            float4 xv = xs4[r * 32 + i4];
            acc[r] += w.x * xv.x + w.y * xv.y + w.z * xv.z + w.w * xv.w;
        }
    }
    float bj = b[j];
#pragma unroll
    for (int r = 0; r < 8; r++) g_att[(rb + r) * 128 + j] = acc[r] + bj;
}

// ---- t1 = task @ W1[:, :128]^T + b1 (b1 folded) ; n1 = attended @ W1[:,128:]^T
__global__ __launch_bounds__(256) void t1n1_kernel(const float* __restrict__ task,
                                                   const float* __restrict__ W1,
                                                   const float* __restrict__ b1) {
    __shared__ float xs[8 * 128];
    int half = blockIdx.x >> 7;
    int rb = (blockIdx.x & 127) * 8;
    const float* src = half ? g_att : task;
    for (int i = threadIdx.x; i < 1024; i += 256) xs[i] = src[rb * 128 + i];
    __syncthreads();
    int j = threadIdx.x;
    const float4* w4 = (const float4*)(W1 + j * 256 + half * 128);
    const float4* xs4 = (const float4*)xs;
    float acc[8] = {0, 0, 0, 0, 0, 0, 0, 0};
#pragma unroll 8
    for (int i4 = 0; i4 < 32; i4++) {
        float4 w = w4[i4];
#pragma unroll
        for (int r = 0; r < 8; r++) {
            float4 xv = xs4[r * 32 + i4];
            acc[r] += w.x * xv.x + w.y * xv.y + w.z * xv.z + w.w * xv.w;
        }
    }
    float addb = half ? 0.f : b1[j];
    float* dst = half ? g_n1 : g_t1;
#pragma unroll
    for (int r = 0; r < 8; r++) dst[(rb + r) * 256 + j] = acc[r] + addb;
}

// ---------------- coordination head (tiny) -----------------------------------
__global__ __launch_bounds__(256) void coord_kernel(const float* __restrict__ Wc1,
                                                    const float* __restrict__ bc1,
                                                    const float* __restrict__ Wc2,
                                                    const float* __restrict__ bc2,
                                                    float* __restrict__ outc) {
    __shared__ float gs[128];
    __shared__ float hid[256];
    int tid = threadIdx.x;
    if (tid < 128) {
        float a0 = 0, a1 = 0, a2 = 0, a3 = 0;
        for (int i = 0; i < 1024; i += 4) {
            a0 += g_att[(i)     * 128 + tid];
            a1 += g_att[(i + 1) * 128 + tid];
            a2 += g_att[(i + 2) * 128 + tid];
            a3 += g_att[(i + 3) * 128 + tid];
        }
        gs[tid] = (a0 + a1 + a2 + a3) * (1.0f / 1024.0f);
    }
    __syncthreads();
    {
        const float* w = Wc1 + tid * 128;
        float acc = 0;
#pragma unroll 8
        for (int c = 0; c < 128; c++) acc += gs[c] * w[c];
        hid[tid] = fmaxf(acc + bc1[tid], 0.f);
    }
    __syncthreads();
    if (tid < 32) {
        const float* w = Wc2 + tid * 256;
        float acc = 0;
#pragma unroll 8
        for (int c = 0; c < 256; c++) acc += hid[c] * w[c];
        outc[tid] = acc + bc2[tid];
    }
}

// ============================================================================
// matching scores: 68.7 GFLOP pairwise MLP, bf16 mma.sync (m16n8k16).
// Cross-tile pipeline: two accumulator sets; epilogue of tile i-1 interleaved
// into MMA k-steps 0..7 of tile i; pack of tile i+1 in k-steps 8..15.
// Single per-tile __syncthreads; parity-double-buffered red + h1 buffers.
// ============================================================================
#define MSTRIDE 264
#define MATCH_SMEM_BYTES (3 * 128 * MSTRIDE * 2 + (128 + 128 + 512) * 4)

__device__ __forceinline__ uint32_t packbf(float lo, float hi) {
    uint32_t r;
    asm("cvt.rn.bf16x2.f32 %0, %1, %2;" : "=r"(r) : "f"(hi), "f"(lo));
    return r;
}

#define LDG128(dst, ptr)                                                        \
    asm volatile("ld.global.nc.v4.f32 {%0,%1,%2,%3}, [%4];"                     \
                 : "=f"((dst).x), "=f"((dst).y), "=f"((dst).z), "=f"((dst).w)   \
                 : "l"(ptr))

__device__ __forceinline__ void load_tile(int tbase, int nbase, int warp,
                                          int lane, float4 tA[2][2],
                                          float4 nA[8][2]) {
    int c0 = lane * 8;
#pragma unroll
    for (int h = 0; h < 2; h++) {
        const float4* p = (const float4*)(g_t1 + (tbase + 2 * warp + h) * 256 + c0);
        LDG128(tA[h][0], p);
        LDG128(tA[h][1], p + 1);
    }
#pragma unroll
    for (int n = 0; n < 8; n++) {
        const float4* p = (const float4*)(g_n1 + (nbase + n) * 256 + c0);
        LDG128(nA[n][0], p);
        LDG128(nA[n][1], p + 1);
    }
}

// pack one n-row pair (rows warp*16+n and warp*16+8+n); b1 pre-folded into t1
__device__ __forceinline__ void pack_rows(__nv_bfloat16* dst, int warp, int lane,
                                          const float4 tA[2][2], float4 N0,
                                          float4 N1, int n) {
    int c0 = lane * 8;
#pragma unroll
    for (int h = 0; h < 2; h++) {
        float4 T0 = tA[h][0], T1 = tA[h][1];
        uint4 pk;
        pk.x = packbf(fmaxf(T0.x + N0.x, 0.f), fmaxf(T0.y + N0.y, 0.f));
        pk.y = packbf(fmaxf(T0.z + N0.z, 0.f), fmaxf(T0.w + N0.w, 0.f));
        pk.z = packbf(fmaxf(T1.x + N1.x, 0.f), fmaxf(T1.y + N1.y, 0.f));
        pk.w = packbf(fmaxf(T1.z + N1.z, 0.f), fmaxf(T1.w + N1.w, 0.f));
        *(uint4*)(dst + (warp * 16 + h * 8 + n) * MSTRIDE + c0) = pk;
    }
}

__device__ __forceinline__ void epi_chunk(const float a[2][8][4], int c, int n0w,
                                          int tig, const float* b2s,
                                          const float* W3s, float part[2][2]) {
    int mt = c >> 3, nt = c & 7;
    int cb = n0w + nt * 8 + tig * 2;
    float w3a = W3s[cb], w3b = W3s[cb + 1];
    float ba = b2s[cb], bb = b2s[cb + 1];
    part[mt][0] += fmaxf(a[mt][nt][0] + ba, 0.f) * w3a +
                   fmaxf(a[mt][nt][1] + bb, 0.f) * w3b;
    part[mt][1] += fmaxf(a[mt][nt][2] + ba, 0.f) * w3a +
                   fmaxf(a[mt][nt][3] + bb, 0.f) * w3b;
}

__device__ __forceinline__ void epi_finish(float part[2][2], int warp, int gid,
                                           int tig, int m0w, float* redp) {
#pragma unroll
    for (int mt = 0; mt < 2; mt++)
#pragma unroll
        for (int hh = 0; hh < 2; hh++) {
            float v = part[mt][hh];
            v += __shfl_xor_sync(0xffffffffu, v, 1);
            v += __shfl_xor_sync(0xffffffffu, v, 2);
            part[mt][hh] = v;
        }
    if (tig == 0) {
        int half = warp & 1;
#pragma unroll
        for (int mt = 0; mt < 2; mt++) {
            int r0 = m0w + mt * 16 + gid;
            redp[r0 * 2 + half] = part[mt][0];
            redp[(r0 + 8) * 2 + half] = part[mt][1];
        }
    }
}

__global__ __launch_bounds__(256, 1) void matching_kernel(
    const float* __restrict__ W2, const float* __restrict__ b2,
    const float* __restrict__ W3, const float* __restrict__ b3p,
    float* __restrict__ out) {
    extern __shared__ char smraw[];
    __nv_bfloat16* W2s = (__nv_bfloat16*)smraw;                 // [128][264]
    __nv_bfloat16* h1buf[2];
    h1buf[0] = W2s + 128 * MSTRIDE;
    h1buf[1] = h1buf[0] + 128 * MSTRIDE;
    float* b2s = (float*)(h1buf[1] + 128 * MSTRIDE);            // [128]
    float* W3s = b2s + 128;                                     // [128]
    float* red = W3s + 128;                                     // [2][128][2]

    int tid = threadIdx.x, lane = tid & 31, warp = tid >> 5;

    for (int i = tid; i < 128 * 256; i += 256) {
        int r = i >> 8, c = i & 255;
        W2s[r * MSTRIDE + c] = __float2bfloat16_rn(W2[i]);
    }
    if (tid < 128) { b2s[tid] = b2[tid]; W3s[tid] = W3[tid]; }
    float b3v = b3p[0];

    int m0w = (warp >> 1) * 32;
    int n0w = (warp & 1) * 64;
    int gid = lane >> 2, tig = lane & 3;

    uint32_t w2_base = (uint32_t)__cvta_generic_to_shared(W2s);
    uint32_t h1_base[2] = {(uint32_t)__cvta_generic_to_shared(h1buf[0]),
                           (uint32_t)__cvta_generic_to_shared(h1buf[1])};
    uint32_t aOff[2];
#pragma unroll
    for (int mt = 0; mt < 2; mt++)
        aOff[mt] = (uint32_t)(((m0w + mt * 16 + (lane & 15)) * MSTRIDE +
                               ((lane >> 4) * 8)) * 2);
    int rowB = (lane & 7) + (((lane >> 4) & 1) << 3);
    int koffB = ((lane >> 3) & 1) * 8;
    uint32_t bAddr[4];
#pragma unroll
    for (int j = 0; j < 4; j++)
        bAddr[j] = w2_base + (uint32_t)(((n0w + j * 16 + rowB) * MSTRIDE + koffB) * 2);

    // prologue: build tile0 into buffer 0
    {
        int tile0 = blockIdx.x;
        float4 tA[2][2], nA[8][2];
        load_tile((tile0 >> 7) * 16, (tile0 & 127) * 8, warp, lane, tA, nA);
#pragma unroll
        for (int n = 0; n < 8; n++)
            pack_rows(h1buf[0], warp, lane, tA, nA[n][0], nA[n][1], n);
    }
    __syncthreads();

    const int GRID = gridDim.x;
    int tile = blockIdx.x;
    int cslot = 0, pslot = 1;
    bool have_prev = false;
    int ptb = 0, pnb = 0;
    float accA[2][8][4], accB[2][8][4];

#define MATCH_BODY(ACCC, ACCP)                                                  \
    {                                                                           \
        bool have_cur = (tile < 8192);                                          \
        int tbase = (tile >> 7) * 16, nbase = (tile & 127) * 8;                 \
        int ntile = tile + GRID;                                                \
        bool have_next = (ntile < 8192);                                        \
        float4 tA[2][2], nA[8][2];                                              \
        if (have_next)                                                          \
            load_tile((ntile >> 7) * 16, (ntile & 127) * 8, warp, lane, tA, nA);\
        float part[2][2] = {{0.f, 0.f}, {0.f, 0.f}};                            \
        float* redp = red + pslot * 256;                                        \
        if (have_cur) {                                                         \
            _Pragma("unroll")                                                   \
            for (int mt = 0; mt < 2; mt++)                                      \
                _Pragma("unroll")                                               \
                for (int nt = 0; nt < 8; nt++)                                  \
                    _Pragma("unroll")                                           \
                    for (int i = 0; i < 4; i++) ACCC[mt][nt][i] = 0.f;          \
            _Pragma("unroll")                                                   \
            for (int ks = 0; ks < 16; ks++) {                                   \
                uint32_t cb = ks * 32;                                          \
                uint32_t a[2][4], bq[4][4];                                     \
                _Pragma("unroll")                                               \
                for (int mt = 0; mt < 2; mt++)                                  \
                    asm volatile(                                               \
                        "ldmatrix.sync.aligned.m8n8.x4.shared.b16 "             \
                        "{%0,%1,%2,%3}, [%4];"                                  \
                        : "=r"(a[mt][0]), "=r"(a[mt][1]), "=r"(a[mt][2]),       \
                          "=r"(a[mt][3])                                        \
                        : "r"(h1_base[cslot] + aOff[mt] + cb));                 \
                _Pragma("unroll")                                               \
                for (int j = 0; j < 4; j++)                                     \
                    asm volatile(                                               \
                        "ldmatrix.sync.aligned.m8n8.x4.shared.b16 "             \
                        "{%0,%1,%2,%3}, [%4];"                                  \
                        : "=r"(bq[j][0]), "=r"(bq[j][1]), "=r"(bq[j][2]),       \
                          "=r"(bq[j][3])                                        \
                        : "r"(bAddr[j] + cb));                                  \
                _Pragma("unroll")                                               \
                for (int mt = 0; mt < 2; mt++)                                  \
                    _Pragma("unroll")                                           \
                    for (int j = 0; j < 4; j++) {                               \
                        asm volatile(                                           \
                            "mma.sync.aligned.m16n8k16.row.col.f32.bf16.bf16.f32 " \
                            "{%0,%1,%2,%3}, {%4,%5,%6,%7}, {%8,%9}, {%0,%1,%2,%3};" \
                            : "+f"(ACCC[mt][2 * j][0]), "+f"(ACCC[mt][2 * j][1]), \
                              "+f"(ACCC[mt][2 * j][2]), "+f"(ACCC[mt][2 * j][3]) \
                            : "r"(a[mt][0]), "r"(a[mt][1]), "r"(a[mt][2]),      \
                              "r"(a[mt][3]), "r"(bq[j][0]), "r"(bq[j][1]));     \
                        asm volatile(                                           \
                            "mma.sync.aligned.m16n8k16.row.col.f32.bf16.bf16.f32 " \
                            "{%0,%1,%2,%3}, {%4,%5,%6,%7}, {%8,%9}, {%0,%1,%2,%3};" \
                            : "+f"(ACCC[mt][2 * j + 1][0]),                     \
                              "+f"(ACCC[mt][2 * j + 1][1]),                     \
                              "+f"(ACCC[mt][2 * j + 1][2]),                     \
                              "+f"(ACCC[mt][2 * j + 1][3])                      \
                            : "r"(a[mt][0]), "r"(a[mt][1]), "r"(a[mt][2]),      \
                              "r"(a[mt][3]), "r"(bq[j][2]), "r"(bq[j][3]));     \
                    }                                                           \
                if (ks < 8 && have_prev) {                                      \
                    epi_chunk(ACCP, 2 * ks, n0w, tig, b2s, W3s, part);          \
                    epi_chunk(ACCP, 2 * ks + 1, n0w, tig, b2s, W3s, part);      \
                }                                                               \
                if (ks >= 8 && have_next)                                       \
                    pack_rows(h1buf[cslot ^ 1], warp, lane, tA, nA[ks - 8][0],  \
                              nA[ks - 8][1], ks - 8);                           \
            }                                                                   \
            if (have_prev) epi_finish(part, warp, gid, tig, m0w, redp);         \
        } else if (have_prev) {                                                 \
            _Pragma("unroll")                                                   \
            for (int c = 0; c < 16; c++)                                        \
                epi_chunk(ACCP, c, n0w, tig, b2s, W3s, part);                   \
            epi_finish(part, warp, gid, tig, m0w, redp);                        \
        }                                                                       \
        __syncthreads();                                                        \
        if (have_prev && tid < 128) {                                           \
            float z = redp[tid * 2] + redp[tid * 2 + 1] + b3v;                  \
            float s = 1.f / (1.f + __expf(-z));                                 \
            out[(ptb + (tid >> 3)) * 1024 + (pnb + (tid & 7))] = s;             \
        }                                                                       \
        have_prev = have_cur;                                                   \
        ptb = tbase; pnb = nbase;                                               \
        pslot = cslot; cslot ^= 1;                                              \
        tile = ntile;                                                           \
    }

    for (;;) {
        MATCH_BODY(accA, accB);
        if (!have_prev && tile >= 8192) break;
        MATCH_BODY(accB, accA);
        if (!have_prev && tile >= 8192) break;
    }
#undef MATCH_BODY
}

// ---------------- launch ------------------------------------------------------
extern "C" void kernel_launch(void* const* d_in, const int* in_sizes, int n_in,
                              void* d_out, int out_size) {
    const float* node_states = (const float*)d_in[0];
    const float* task_features = (const float*)d_in[1];
    const float* in_proj_w = (const float*)d_in[2];
    const float* in_proj_b = (const float*)d_in[3];
    const float* out_w = (const float*)d_in[4];
    const float* out_b = (const float*)d_in[5];
    const float* W1 = (const float*)d_in[6];
    const float* b1 = (const float*)d_in[7];
    const float* W2 = (const float*)d_in[8];
    const float* b2 = (const float*)d_in[9];
    const float* W3 = (const float*)d_in[10];
    const float* b3 = (const float*)d_in[11];
    const float* Wc1 = (const float*)d_in[12];
    const float* bc1 = (const float*)d_in[13];
    const float* Wc2 = (const float*)d_in[14];
    const float* bc2 = (const float*)d_in[15];

    float* out = (float*)d_out;
    float* matching = out;                       // [1024*1024]
    float* coord = out + 1024 * 1024;            // [32]
    float* attnw = out + 1024 * 1024 + 32;       // [1024*1024]

    cudaFuncSetAttribute((const void*)attn_kernel,
                         cudaFuncAttributeMaxDynamicSharedMemorySize, ATTN_SMEM_BYTES);
    cudaFuncSetAttribute((const void*)matching_kernel,
                         cudaFuncAttributeMaxDynamicSharedMemorySize, MATCH_SMEM_BYTES);

    qkv_kernel<<<128, 384>>>(node_states, in_proj_w, in_proj_b);
    attn_kernel<<<128, 256, ATTN_SMEM_BYTES>>>(attnw);
    outproj_kernel<<<128, 128>>>(out_w, out_b);
    t1n1_kernel<<<256, 256>>>(task_features, W1, b1);
    coord_kernel<<<1, 256>>>(Wc1, bc1, Wc2, bc2, coord);
    matching_kernel<<<148, 256, MATCH_SMEM_BYTES>>>(W2, b2, W3, b3, matching);
}